// round 7
// baseline (speedup 1.0000x reference)
#include <cuda_runtime.h>
#include <cstdint>

#define NMAX 50000
#define EMAX 650000
#define H 128
#define KTOT 256
#define TPB 512

// -------------------- scratch (no allocations allowed) ----------------------
__device__ float g_h0[NMAX * H];
__device__ float g_h1[NMAX * H];
__device__ float g_agg[NMAX * H];
__device__ int   g_cnt[NMAX];
__device__ int   g_off[NMAX];
__device__ int   g_cur[NMAX];
__device__ int   g_adj[EMAX];
__device__ int   g_blk[256];

// -------------------- helpers ------------------------------------------------
__device__ __forceinline__ uint32_t tf32r(float x) {
    uint32_t r; asm("cvt.rna.tf32.f32 %0, %1;" : "=r"(r) : "f"(x));
    return r;
}
__device__ __forceinline__ void mma_tf32(float* d, const uint32_t* a, const uint32_t* b) {
    asm volatile("mma.sync.aligned.m16n8k8.row.col.f32.tf32.tf32.f32 "
                 "{%0,%1,%2,%3}, {%4,%5,%6,%7}, {%8,%9}, {%0,%1,%2,%3};"
                 : "+f"(d[0]), "+f"(d[1]), "+f"(d[2]), "+f"(d[3])
                 : "r"(a[0]), "r"(a[1]), "r"(a[2]), "r"(a[3]),
                   "r"(b[0]), "r"(b[1]));
}

// -------------------- CSR build ----------------------------------------------
__global__ void zero_cnt(int n) {
    int i = blockIdx.x * blockDim.x + threadIdx.x;
    if (i < n) g_cnt[i] = 0;
}
__global__ void hist_kernel(const int* __restrict__ ei, int E) {
    int e = blockIdx.x * blockDim.x + threadIdx.x;
    if (e < E) atomicAdd(&g_cnt[__ldg(ei + E + e)], 1);
}
__global__ void scan1(int n) {
    __shared__ int smv[256];
    int t = threadIdx.x;
    int i = blockIdx.x * 256 + t;
    int v = (i < n) ? g_cnt[i] : 0;
    smv[t] = v;
    __syncthreads();
    #pragma unroll
    for (int off = 1; off < 256; off <<= 1) {
        int x = (t >= off) ? smv[t - off] : 0;
        __syncthreads();
        smv[t] += x;
        __syncthreads();
    }
    if (i < n) g_off[i] = smv[t] - v;
    if (t == 255) g_blk[blockIdx.x] = smv[255];
}
__global__ void scan2(int nb) {
    __shared__ int smv[256];
    int t = threadIdx.x;
    int v = (t < nb) ? g_blk[t] : 0;
    smv[t] = v;
    __syncthreads();
    #pragma unroll
    for (int off = 1; off < 256; off <<= 1) {
        int x = (t >= off) ? smv[t - off] : 0;
        __syncthreads();
        smv[t] += x;
        __syncthreads();
    }
    if (t < nb) g_blk[t] = smv[t] - v;
}
__global__ void scan3(int n) {
    int i = blockIdx.x * blockDim.x + threadIdx.x;
    if (i < n) {
        int o = g_off[i] + g_blk[i >> 8];
        g_off[i] = o;
        g_cur[i] = o;
    }
}
__global__ void fill_kernel(const int* __restrict__ ei, int E) {
    int e = blockIdx.x * blockDim.x + threadIdx.x;
    if (e < E) {
        int s = __ldg(ei + e);
        int d = __ldg(ei + E + e);
        int p = atomicAdd(&g_cur[d], 1);
        g_adj[p] = s;
    }
}

// -------------------- CSR aggregate: mean of h[src] per dst ------------------
template<int SRC>
__global__ void aggregate_kernel(int n) {
    int gw = (blockIdx.x * blockDim.x + threadIdx.x) >> 5;
    if (gw >= n) return;
    int lane = threadIdx.x & 31;
    const float* h = (SRC == 0) ? g_h0 : g_h1;
    int start = g_off[gw];
    int c = g_cnt[gw];
    float4 acc0 = make_float4(0.f, 0.f, 0.f, 0.f);
    float4 acc1 = make_float4(0.f, 0.f, 0.f, 0.f);
    int j = 0;
    for (; j + 2 <= c; j += 2) {
        int s0 = __ldg(g_adj + start + j);
        int s1 = __ldg(g_adj + start + j + 1);
        float4 v0 = __ldg((const float4*)(h + (size_t)s0 * H) + lane);
        float4 v1 = __ldg((const float4*)(h + (size_t)s1 * H) + lane);
        acc0.x += v0.x; acc0.y += v0.y; acc0.z += v0.z; acc0.w += v0.w;
        acc1.x += v1.x; acc1.y += v1.y; acc1.z += v1.z; acc1.w += v1.w;
    }
    if (j < c) {
        int s0 = __ldg(g_adj + start + j);
        float4 v0 = __ldg((const float4*)(h + (size_t)s0 * H) + lane);
        acc0.x += v0.x; acc0.y += v0.y; acc0.z += v0.z; acc0.w += v0.w;
    }
    float sc = (c > 0) ? (1.0f / (float)c) : 0.0f;
    float4 o;
    o.x = (acc0.x + acc1.x) * sc;
    o.y = (acc0.y + acc1.y) * sc;
    o.z = (acc0.z + acc1.z) * sc;
    o.w = (acc0.w + acc1.w) * sc;
    ((float4*)(g_agg + (size_t)gw * H))[lane] = o;
}

// smem layout (floats)
#define WROW      264                     // k-pair row stride: 256 + 8 pad
#define SMF_W     0                       // 128 pair-rows * 264 = 33792 (135 KB)
#define SMF_A     33792                   // 2 * 128*32 = 8192
#define SMF_C     41984                   // 768
#define SMF_RS    42752                   // 512
#define SMF_RSS   43264                   // 512
#define SMF_MU    43776                   // 128
#define SMF_RSTD  43904                   // 128
#define SMF_KIND  44032                   // 128
#define SMF_TOTAL 44160
#define SM_BYTES  (SMF_TOTAL * 4)

// -------------------- persistent tf32 mma GEMM, W resident ------------------
// MODE 0: A=x[N,256], W=W_in            -> h0 = ..+b_in+kind_embed[k]+relay*ext
// MODE 1: A=[agg | h0], W=[Wl1;Wr1]     -> relu(LN(..+bl1)) -> h1
// MODE 2: A=[agg | h1], W=[Wl2;Wr2]     -> ..+bl2 -> out
template<int MODE>
__global__ void __launch_bounds__(TPB, 1)
tc_gemm(const float* __restrict__ Aext,
        const float* __restrict__ W0,
        const float* __restrict__ W1,
        const float* __restrict__ bias,
        const float* __restrict__ aux0,   // MODE0 kind_embed / MODE1 gamma
        const float* __restrict__ aux1,   // MODE0 ext_seed   / MODE1 beta
        const int*   __restrict__ node_kind,
        float* __restrict__ outExt,
        int n)
{
    extern __shared__ float sm[];
    float* Wsh   = sm + SMF_W;
    float* Abuf[2] = { sm + SMF_A, sm + SMF_A + 128 * 32 };
    float* csh   = sm + SMF_C;
    float* rs    = sm + SMF_RS;
    float* rss   = sm + SMF_RSS;
    float* mus   = sm + SMF_MU;
    float* rstds = sm + SMF_RSTD;
    int*   kindsh = (int*)(sm + SMF_KIND);

    const int tid = threadIdx.x;
    const int wid = tid >> 5;
    const int lid = tid & 31;
    const int lq = lid >> 2;
    const int lr = lid & 3;
    const int wr = wid & 3;        // 4 row-blocks of 32
    const int cw = wid >> 2;       // 4 col-blocks of 32

    // A staging roles
    const int arow = tid >> 2;     // 0..127
    const int ag   = tid & 3;      // k-group of 8

    const float* Asrc = (MODE == 1) ? (const float*)g_h0 : (const float*)g_h1;

    // ---- stage consts ----
    if (tid < H) csh[tid] = __ldg(bias + tid);
    if (MODE == 0) {
        if (tid >= H && tid < H + 3 * H) csh[tid] = __ldg(aux0 + (tid - H));
        if (tid < H) csh[4 * H + tid] = __ldg(aux1 + tid);
    } else if (MODE == 1) {
        if (tid < H) { csh[H + tid] = __ldg(aux0 + tid); csh[2 * H + tid] = __ldg(aux1 + tid); }
    }

    // ---- stage W once per CTA: k-pair interleaved layout ----
    // pair-row (c*16 + pr) holds k1 = c*32 + (pr>>2)*8 + (pr&3) at even slots,
    // k2 = k1 + 4 at odd slots; element (k, col) -> [(c*16+pr)*WROW + col*2 + s]
    for (int i = tid; i < KTOT * 32; i += TPB) {   // 8192 float4 units
        int k  = i >> 5;
        int q4 = i & 31;
        const float* row = (MODE == 0 || k < H) ? W0 + (size_t)k * H
                                                : W1 + (size_t)(k - H) * H;
        float4 v = __ldg((const float4*)row + q4);
        int c  = k >> 5, kk = k & 31;
        int pr = ((kk >> 3) << 2) | (kk & 3);
        int s  = (kk >> 2) & 1;
        float* base = &Wsh[(c * 16 + pr) * WROW + s];
        base[(q4 * 4 + 0) * 2] = __uint_as_float(tf32r(v.x));
        base[(q4 * 4 + 1) * 2] = __uint_as_float(tf32r(v.y));
        base[(q4 * 4 + 2) * 2] = __uint_as_float(tf32r(v.z));
        base[(q4 * 4 + 3) * 2] = __uint_as_float(tf32r(v.w));
    }

    int ntiles = (n + 127) >> 7;

    for (int tile = blockIdx.x; tile < ntiles; tile += gridDim.x) {
        const int row0 = tile << 7;
        const int agr  = row0 + arow;

        float4 va, vb;
        auto ldgA = [&](int ch) {
            va = make_float4(0.f,0.f,0.f,0.f); vb = va;
            if (agr < n) {
                if (MODE == 0) {
                    const float4* s = (const float4*)(Aext + (size_t)agr * KTOT + ch * 32 + ag * 8);
                    va = __ldg(s); vb = __ldg(s + 1);
                } else if (ch < 4) {
                    const float4* s = (const float4*)(g_agg + (size_t)agr * H + ch * 32 + ag * 8);
                    va = __ldg(s); vb = __ldg(s + 1);
                } else {
                    const float4* s = (const float4*)(Asrc + (size_t)agr * H + (ch - 4) * 32 + ag * 8);
                    va = __ldg(s); vb = __ldg(s + 1);
                }
            }
        };
        auto stsA = [&](int p) {
            uint4 s0, s1;
            s0.x = tf32r(va.x); s0.y = tf32r(vb.x);
            s0.z = tf32r(va.y); s0.w = tf32r(vb.y);
            s1.x = tf32r(va.z); s1.y = tf32r(vb.z);
            s1.z = tf32r(va.w); s1.w = tf32r(vb.w);
            int u0 = (ag * 2) ^ ((arow & 3) << 1);
            uint4* d = (uint4*)&Abuf[p][arow * 32 + u0 * 4];
            d[0] = s0; d[1] = s1;
        };

        // ---- per-tile prologue ----
        ldgA(0);
        if (MODE == 0 && tid < 128)
            kindsh[tid] = (row0 + tid < n) ? __ldg(node_kind + row0 + tid) : 0;
        __syncthreads();          // prior tile fully done; W staged (first tile)
        stsA(0);
        ldgA(1);
        __syncthreads();

        float acc[2][4][4];
        #pragma unroll
        for (int mf = 0; mf < 2; mf++)
            #pragma unroll
            for (int nf = 0; nf < 4; nf++)
                #pragma unroll
                for (int q = 0; q < 4; q++) acc[mf][nf][q] = 0.f;

        int p = 0;
        #pragma unroll
        for (int ch = 0; ch < 8; ch++) {
            const float* Ab = Abuf[p];
            const float* Wb = Wsh + ch * 16 * WROW;
            #pragma unroll
            for (int ks = 0; ks < 4; ks++) {
                uint32_t a[2][4];
                #pragma unroll
                for (int mf = 0; mf < 2; mf++) {
                    int rlo = wr * 32 + mf * 16 + lq;
                    int u = (ks * 2 + (lr >> 1)) ^ ((lq & 3) << 1);
                    float2 lo = *(const float2*)&Ab[rlo * 32 + u * 4 + (lr & 1) * 2];
                    float2 hi = *(const float2*)&Ab[(rlo + 8) * 32 + u * 4 + (lr & 1) * 2];
                    a[mf][0] = __float_as_uint(lo.x);
                    a[mf][1] = __float_as_uint(hi.x);
                    a[mf][2] = __float_as_uint(lo.y);
                    a[mf][3] = __float_as_uint(hi.y);
                }
                uint32_t b[4][2];
                #pragma unroll
                for (int nf = 0; nf < 4; nf++) {
                    float2 bv = *(const float2*)&Wb[(ks * 4 + lr) * WROW
                                                    + (cw * 32 + nf * 8 + lq) * 2];
                    b[nf][0] = __float_as_uint(bv.x);
                    b[nf][1] = __float_as_uint(bv.y);
                }
                #pragma unroll
                for (int mf = 0; mf < 2; mf++)
                    #pragma unroll
                    for (int nf = 0; nf < 4; nf++)
                        mma_tf32(acc[mf][nf], a[mf], b[nf]);
            }
            if (ch < 7) {
                stsA(p ^ 1);
                if (ch < 6) ldgA(ch + 2);
            }
            __syncthreads();
            p ^= 1;
        }

        // ---------------- epilogue ----------------
        #pragma unroll
        for (int mf = 0; mf < 2; mf++)
            #pragma unroll
            for (int nf = 0; nf < 4; nf++) {
                int c0 = cw * 32 + nf * 8 + 2 * lr;
                float b0v = csh[c0], b1v = csh[c0 + 1];
                acc[mf][nf][0] += b0v; acc[mf][nf][1] += b1v;
                acc[mf][nf][2] += b0v; acc[mf][nf][3] += b1v;
            }

        if (MODE == 1) {
            #pragma unroll
            for (int mf = 0; mf < 2; mf++) {
                float slo = 0.f, sslo = 0.f, shi = 0.f, sshi = 0.f;
                #pragma unroll
                for (int nf = 0; nf < 4; nf++) {
                    float v0 = acc[mf][nf][0], v1 = acc[mf][nf][1];
                    float v2 = acc[mf][nf][2], v3 = acc[mf][nf][3];
                    slo += v0 + v1;  sslo += v0 * v0 + v1 * v1;
                    shi += v2 + v3;  sshi += v2 * v2 + v3 * v3;
                }
                #pragma unroll
                for (int m = 1; m <= 2; m <<= 1) {
                    slo  += __shfl_xor_sync(0xffffffffu, slo,  m);
                    sslo += __shfl_xor_sync(0xffffffffu, sslo, m);
                    shi  += __shfl_xor_sync(0xffffffffu, shi,  m);
                    sshi += __shfl_xor_sync(0xffffffffu, sshi, m);
                }
                if (lr == 0) {
                    int rlo = wr * 32 + mf * 16 + lq;
                    rs [rlo * 4 + cw] = slo;       rss[rlo * 4 + cw] = sslo;
                    rs [(rlo + 8) * 4 + cw] = shi; rss[(rlo + 8) * 4 + cw] = sshi;
                }
            }
            __syncthreads();
            if (tid < 128) {
                float s  = rs [tid * 4] + rs [tid * 4 + 1] + rs [tid * 4 + 2] + rs [tid * 4 + 3];
                float ss = rss[tid * 4] + rss[tid * 4 + 1] + rss[tid * 4 + 2] + rss[tid * 4 + 3];
                float mu  = s * (1.0f / H);
                float var = ss * (1.0f / H) - mu * mu;
                mus[tid] = mu;
                rstds[tid] = rsqrtf(var + 1e-5f);
            }
            __syncthreads();
            #pragma unroll
            for (int mf = 0; mf < 2; mf++) {
                int lrow = wr * 32 + mf * 16 + lq;
                float mu_lo = mus[lrow],     rd_lo = rstds[lrow];
                float mu_hi = mus[lrow + 8], rd_hi = rstds[lrow + 8];
                int glo = row0 + lrow, ghi = glo + 8;
                #pragma unroll
                for (int nf = 0; nf < 4; nf++) {
                    int c0 = cw * 32 + nf * 8 + 2 * lr;
                    float g0 = csh[H + c0], g1 = csh[H + c0 + 1];
                    float be0 = csh[2 * H + c0], be1 = csh[2 * H + c0 + 1];
                    if (glo < n) {
                        float2 o;
                        o.x = fmaxf((acc[mf][nf][0] - mu_lo) * rd_lo * g0 + be0, 0.f);
                        o.y = fmaxf((acc[mf][nf][1] - mu_lo) * rd_lo * g1 + be1, 0.f);
                        *(float2*)(g_h1 + (size_t)glo * H + c0) = o;
                    }
                    if (ghi < n) {
                        float2 o;
                        o.x = fmaxf((acc[mf][nf][2] - mu_hi) * rd_hi * g0 + be0, 0.f);
                        o.y = fmaxf((acc[mf][nf][3] - mu_hi) * rd_hi * g1 + be1, 0.f);
                        *(float2*)(g_h1 + (size_t)ghi * H + c0) = o;
                    }
                }
            }
        } else {
            #pragma unroll
            for (int mf = 0; mf < 2; mf++) {
                int lrow = wr * 32 + mf * 16 + lq;
                int glo = row0 + lrow, ghi = glo + 8;
                int klo = 0, khi = 0;
                bool rlo = false, rhi = false;
                if (MODE == 0) {
                    klo = kindsh[lrow]; khi = kindsh[lrow + 8];
                    rlo = (klo != 0);   rhi = (khi != 0);
                }
                float* dst = (MODE == 0) ? g_h0 : outExt;
                #pragma unroll
                for (int nf = 0; nf < 4; nf++) {
                    int c0 = cw * 32 + nf * 8 + 2 * lr;
                    if (glo < n) {
                        float2 o = make_float2(acc[mf][nf][0], acc[mf][nf][1]);
                        if (MODE == 0) {
                            o.x += csh[H + klo * H + c0];
                            o.y += csh[H + klo * H + c0 + 1];
                            if (rlo) { o.x += csh[4 * H + c0]; o.y += csh[4 * H + c0 + 1]; }
                        }
                        *(float2*)(dst + (size_t)glo * H + c0) = o;
                    }
                    if (ghi < n) {
                        float2 o = make_float2(acc[mf][nf][2], acc[mf][nf][3]);
                        if (MODE == 0) {
                            o.x += csh[H + khi * H + c0];
                            o.y += csh[H + khi * H + c0 + 1];
                            if (rhi) { o.x += csh[4 * H + c0]; o.y += csh[4 * H + c0 + 1]; }
                        }
                        *(float2*)(dst + (size_t)ghi * H + c0) = o;
                    }
                }
            }
        }
    }
}

// ---------------------------------------------------------------------------
extern "C" void kernel_launch(void* const* d_in, const int* in_sizes, int n_in,
                              void* d_out, int out_size) {
    const float* x          = (const float*)d_in[0];
    const int*   ei         = (const int*)d_in[1];
    const int*   node_kind  = (const int*)d_in[2];
    const float* W_in       = (const float*)d_in[3];
    const float* b_in       = (const float*)d_in[4];
    const float* kind_embed = (const float*)d_in[5];
    const float* ext_seed   = (const float*)d_in[6];
    const float* Wl1        = (const float*)d_in[7];
    const float* bl1        = (const float*)d_in[8];
    const float* Wr1        = (const float*)d_in[9];
    const float* gamma      = (const float*)d_in[10];
    const float* beta       = (const float*)d_in[11];
    const float* Wl2        = (const float*)d_in[12];
    const float* bl2        = (const float*)d_in[13];
    const float* Wr2        = (const float*)d_in[14];

    int n = in_sizes[2];
    int E = in_sizes[1] / 2;

    cudaFuncSetAttribute(tc_gemm<0>, cudaFuncAttributeMaxDynamicSharedMemorySize, SM_BYTES);
    cudaFuncSetAttribute(tc_gemm<1>, cudaFuncAttributeMaxDynamicSharedMemorySize, SM_BYTES);
    cudaFuncSetAttribute(tc_gemm<2>, cudaFuncAttributeMaxDynamicSharedMemorySize, SM_BYTES);

    int ntiles = (n + 127) / 128;
    int ggrid  = ntiles < 148 ? ntiles : 148;
    int nb256  = (n + 255) / 256;
    int eb256  = (E + 255) / 256;
    int aggblk = (n * 32 + 255) / 256;

    // ---- fork: CSR build on side stream, concurrent with gemm0 ----
    cudaStream_t s2;
    cudaStreamCreateWithFlags(&s2, cudaStreamNonBlocking);
    cudaEvent_t e1, e2;
    cudaEventCreateWithFlags(&e1, cudaEventDisableTiming);
    cudaEventCreateWithFlags(&e2, cudaEventDisableTiming);

    cudaEventRecord(e1, 0);
    cudaStreamWaitEvent(s2, e1, 0);
    zero_cnt<<<nb256, 256, 0, s2>>>(n);
    hist_kernel<<<eb256, 256, 0, s2>>>(ei, E);
    scan1<<<nb256, 256, 0, s2>>>(n);
    scan2<<<1, 256, 0, s2>>>(nb256);
    scan3<<<nb256, 256, 0, s2>>>(n);
    fill_kernel<<<eb256, 256, 0, s2>>>(ei, E);
    cudaEventRecord(e2, s2);

    // gemm0 on main stream, overlapping the CSR chain
    tc_gemm<0><<<ggrid, TPB, SM_BYTES>>>(x, W_in, nullptr, b_in, kind_embed,
                                         ext_seed, node_kind, nullptr, n);

    // ---- join: aggregate needs both h0 and CSR ----
    cudaStreamWaitEvent(0, e2, 0);
    aggregate_kernel<0><<<aggblk, 256>>>(n);
    tc_gemm<1><<<ggrid, TPB, SM_BYTES>>>(nullptr, Wl1, Wr1, bl1, gamma, beta,
                                         nullptr, nullptr, n);
    aggregate_kernel<1><<<aggblk, 256>>>(n);
    tc_gemm<2><<<ggrid, TPB, SM_BYTES>>>(nullptr, Wl2, Wr2, bl2, nullptr, nullptr,
                                         nullptr, (float*)d_out, n);
}

// round 9
// speedup vs baseline: 1.0041x; 1.0041x over previous
#include <cuda_runtime.h>
#include <cstdint>

#define NMAX 50000
#define EMAX 650000
#define H 128
#define KTOT 256
#define TPB 256
#define WROW 264   // k-pair row stride: 256 + 8 pad

// -------------------- scratch (no allocations allowed) ----------------------
__device__ float g_h0[NMAX * H];
__device__ float g_h1[NMAX * H];
__device__ float g_agg[NMAX * H];
__device__ int   g_cnt[NMAX];
__device__ int   g_off[NMAX];
__device__ int   g_cur[NMAX];
__device__ int   g_adj[EMAX];
__device__ int   g_blk[256];
__device__ float g_Wt[3][128 * WROW];   // tf32-rounded, smem-image layout

// -------------------- helpers ------------------------------------------------
__device__ __forceinline__ uint32_t tf32r(float x) {
    uint32_t r; asm("cvt.rna.tf32.f32 %0, %1;" : "=r"(r) : "f"(x));
    return r;
}
__device__ __forceinline__ void mma_tf32(float* d, const uint32_t* a, const uint32_t* b) {
    asm volatile("mma.sync.aligned.m16n8k8.row.col.f32.tf32.tf32.f32 "
                 "{%0,%1,%2,%3}, {%4,%5,%6,%7}, {%8,%9}, {%0,%1,%2,%3};"
                 : "+f"(d[0]), "+f"(d[1]), "+f"(d[2]), "+f"(d[3])
                 : "r"(a[0]), "r"(a[1]), "r"(a[2]), "r"(a[3]),
                   "r"(b[0]), "r"(b[1]));
}
__device__ __forceinline__ void cp16(uint32_t dst, const float* src) {
    asm volatile("cp.async.cg.shared.global [%0], [%1], 16;" :: "r"(dst), "l"(src));
}
__device__ __forceinline__ void cp_commit() {
    asm volatile("cp.async.commit_group;" ::: "memory");
}
template<int N>
__device__ __forceinline__ void cp_wait() {
    asm volatile("cp.async.wait_group %0;" :: "n"(N) : "memory");
}

// -------------------- weight prep: tf32-round into smem-image layout ---------
__global__ void prep_w(const float* __restrict__ W_in,
                       const float* __restrict__ Wl1, const float* __restrict__ Wr1,
                       const float* __restrict__ Wl2, const float* __restrict__ Wr2) {
    int i = blockIdx.x * blockDim.x + threadIdx.x;
    if (i >= 3 * KTOT * H) return;
    int col = i & 127;
    int k   = (i >> 7) & 255;
    int m   = i >> 15;
    float v;
    if (m == 0)      v = W_in[k * H + col];
    else if (m == 1) v = (k < H) ? Wl1[k * H + col] : Wr1[(k - H) * H + col];
    else             v = (k < H) ? Wl2[k * H + col] : Wr2[(k - H) * H + col];
    int c  = k >> 5, kk = k & 31;
    int pr = ((kk >> 3) << 2) | (kk & 3);
    int s  = (kk >> 2) & 1;
    g_Wt[m][(c * 16 + pr) * WROW + col * 2 + s] = __uint_as_float(tf32r(v));
}

// -------------------- CSR build ----------------------------------------------
__global__ void zero_cnt(int n) {
    int i = blockIdx.x * blockDim.x + threadIdx.x;
    if (i < n) g_cnt[i] = 0;
}
__global__ void hist_kernel(const int* __restrict__ ei, int E) {
    int e = blockIdx.x * blockDim.x + threadIdx.x;
    if (e < E) atomicAdd(&g_cnt[__ldg(ei + E + e)], 1);
}
__global__ void scan1(int n) {
    __shared__ int smv[256];
    int t = threadIdx.x;
    int i = blockIdx.x * 256 + t;
    int v = (i < n) ? g_cnt[i] : 0;
    smv[t] = v;
    __syncthreads();
    #pragma unroll
    for (int off = 1; off < 256; off <<= 1) {
        int x = (t >= off) ? smv[t - off] : 0;
        __syncthreads();
        smv[t] += x;
        __syncthreads();
    }
    if (i < n) g_off[i] = smv[t] - v;
    if (t == 255) g_blk[blockIdx.x] = smv[255];
}
__global__ void scan2(int nb) {
    __shared__ int smv[256];
    int t = threadIdx.x;
    int v = (t < nb) ? g_blk[t] : 0;
    smv[t] = v;
    __syncthreads();
    #pragma unroll
    for (int off = 1; off < 256; off <<= 1) {
        int x = (t >= off) ? smv[t - off] : 0;
        __syncthreads();
        smv[t] += x;
        __syncthreads();
    }
    if (t < nb) g_blk[t] = smv[t] - v;
}
__global__ void scan3(int n) {
    int i = blockIdx.x * blockDim.x + threadIdx.x;
    if (i < n) {
        int o = g_off[i] + g_blk[i >> 8];
        g_off[i] = o;
        g_cur[i] = o;
    }
}
__global__ void fill_kernel(const int* __restrict__ ei, int E) {
    int e = blockIdx.x * blockDim.x + threadIdx.x;
    if (e < E) {
        int s = __ldg(ei + e);
        int d = __ldg(ei + E + e);
        int p = atomicAdd(&g_cur[d], 1);
        g_adj[p] = s;
    }
}

// -------------------- CSR aggregate: mean of h[src] per dst ------------------
template<int SRC>
__global__ void aggregate_kernel(int n) {
    int gw = (blockIdx.x * blockDim.x + threadIdx.x) >> 5;
    if (gw >= n) return;
    int lane = threadIdx.x & 31;
    const float* h = (SRC == 0) ? g_h0 : g_h1;
    int start = g_off[gw];
    int c = g_cnt[gw];
    float4 acc0 = make_float4(0.f, 0.f, 0.f, 0.f);
    float4 acc1 = make_float4(0.f, 0.f, 0.f, 0.f);
    int j = 0;
    for (; j + 2 <= c; j += 2) {
        int s0 = __ldg(g_adj + start + j);
        int s1 = __ldg(g_adj + start + j + 1);
        float4 v0 = __ldg((const float4*)(h + (size_t)s0 * H) + lane);
        float4 v1 = __ldg((const float4*)(h + (size_t)s1 * H) + lane);
        acc0.x += v0.x; acc0.y += v0.y; acc0.z += v0.z; acc0.w += v0.w;
        acc1.x += v1.x; acc1.y += v1.y; acc1.z += v1.z; acc1.w += v1.w;
    }
    if (j < c) {
        int s0 = __ldg(g_adj + start + j);
        float4 v0 = __ldg((const float4*)(h + (size_t)s0 * H) + lane);
        acc0.x += v0.x; acc0.y += v0.y; acc0.z += v0.z; acc0.w += v0.w;
    }
    float sc = (c > 0) ? (1.0f / (float)c) : 0.0f;
    float4 o;
    o.x = (acc0.x + acc1.x) * sc;
    o.y = (acc0.y + acc1.y) * sc;
    o.z = (acc0.z + acc1.z) * sc;
    o.w = (acc0.w + acc1.w) * sc;
    ((float4*)(g_agg + (size_t)gw * H))[lane] = o;
}

// smem layout (floats)
#define SMF_W     0                       // 2 * 16*264 = 8448
#define SMF_A     8448                    // 2 * 128*32 = 8192
#define SMF_C     16640                   // 768
#define SMF_RS    17408                   // 512
#define SMF_RSS   17920                   // 512
#define SMF_MU    18432                   // 128
#define SMF_RSTD  18560                   // 128
#define SMF_KIND  18688                   // 128
#define SMF_TOTAL 18816
#define SM_BYTES  (SMF_TOTAL * 4)

// -------------------- pipelined tf32 mma GEMM, 8 warps, 2 CTA/SM -------------
// MODE 0: A=x[N,256], W=Wt0 -> h0 = ..+b_in+kind_embed[k]+relay*ext
// MODE 1: A=[agg | h0], W=Wt1 -> relu(LN(..+bl1)) -> h1
// MODE 2: A=[agg | h1], W=Wt2 -> ..+bl2 -> out
template<int MODE>
__global__ void __launch_bounds__(TPB, 2)
tc_gemm(const float* __restrict__ Aext,
        const float* __restrict__ bias,
        const float* __restrict__ aux0,   // MODE0 kind_embed / MODE1 gamma
        const float* __restrict__ aux1,   // MODE0 ext_seed   / MODE1 beta
        const int*   __restrict__ node_kind,
        float* __restrict__ outExt,
        int n)
{
    extern __shared__ float sm[];
    float* Wbuf[2] = { sm + SMF_W, sm + SMF_W + 16 * WROW };
    float* Abuf[2] = { sm + SMF_A, sm + SMF_A + 128 * 32 };
    float* csh   = sm + SMF_C;
    float* rs    = sm + SMF_RS;
    float* rss   = sm + SMF_RSS;
    float* mus   = sm + SMF_MU;
    float* rstds = sm + SMF_RSTD;
    int*   kindsh = (int*)(sm + SMF_KIND);

    const int tid = threadIdx.x;
    const int wid = tid >> 5;
    const int lid = tid & 31;
    const int lq = lid >> 2;
    const int lr = lid & 3;
    const int wr = wid & 1;        // 2 row-blocks of 64
    const int cw = wid >> 1;       // 4 col-blocks of 32
    const int row0 = blockIdx.x << 7;

    // A staging roles: 2 threads per row, each 16 consecutive k floats
    const int arow  = tid >> 1;    // 0..127
    const int khalf = tid & 1;     // 0/1 -> k offset 0/16
    const int agr   = row0 + arow;

    const float* Asrc = (MODE == 1) ? (const float*)g_h0 : (const float*)g_h1;
    const float* Wt = g_Wt[MODE];

    uint32_t wsh[2] = { (uint32_t)__cvta_generic_to_shared(Wbuf[0]),
                        (uint32_t)__cvta_generic_to_shared(Wbuf[1]) };

    float4 va0, va1, va2, va3;

    auto ldgA = [&](int ch) {
        va0 = make_float4(0.f,0.f,0.f,0.f); va1 = va0; va2 = va0; va3 = va0;
        if (agr < n) {
            const float4* s;
            if (MODE == 0)      s = (const float4*)(Aext  + (size_t)agr * KTOT + ch * 32 + khalf * 16);
            else if (ch < 4)    s = (const float4*)(g_agg + (size_t)agr * H + ch * 32 + khalf * 16);
            else                s = (const float4*)(Asrc  + (size_t)agr * H + (ch - 4) * 32 + khalf * 16);
            va0 = __ldg(s); va1 = __ldg(s + 1); va2 = __ldg(s + 2); va3 = __ldg(s + 3);
        }
    };
    auto stsA = [&](int p) {
        #pragma unroll
        for (int g = 0; g < 2; g++) {
            float4 va = g ? va2 : va0;
            float4 vb = g ? va3 : va1;
            int ag = khalf * 2 + g;
            uint4 s0, s1;
            s0.x = tf32r(va.x); s0.y = tf32r(vb.x);
            s0.z = tf32r(va.y); s0.w = tf32r(vb.y);
            s1.x = tf32r(va.z); s1.y = tf32r(vb.z);
            s1.z = tf32r(va.w); s1.w = tf32r(vb.w);
            int u0 = (ag * 2) ^ ((arow & 3) << 1);
            uint4* d = (uint4*)&Abuf[p][arow * 32 + u0 * 4];
            d[0] = s0; d[1] = s1;
        }
    };
    auto copyW = [&](int ch, int p) {
        const float* src = Wt + ch * 16 * WROW;
        #pragma unroll
        for (int j = 0; j < 4; j++) {
            int f4  = tid * 4 + j;           // 0..1023
            int r   = f4 >> 6;               // pair-row 0..15
            int q   = f4 & 63;               // float4 within row
            int off = r * WROW + q * 4;
            cp16(wsh[p] + off * 4, src + off);
        }
    };

    // ---- prologue: W chunks 0,1 in flight; consts; A chunk 0 staged ----
    copyW(0, 0); cp_commit();
    copyW(1, 1); cp_commit();
    ldgA(0);
    if (tid < H) csh[tid] = __ldg(bias + tid);
    if (MODE == 0) {
        for (int i = tid; i < 3 * H; i += TPB) csh[H + i] = __ldg(aux0 + i);
        if (tid < H) csh[4 * H + tid] = __ldg(aux1 + tid);
        if (tid < 128) kindsh[tid] = (row0 + tid < n) ? __ldg(node_kind + row0 + tid) : 0;
    } else if (MODE == 1) {
        if (tid < H) { csh[H + tid] = __ldg(aux0 + tid); csh[2 * H + tid] = __ldg(aux1 + tid); }
    }
    stsA(0);
    ldgA(1);
    cp_wait<1>();      // W chunk 0 landed
    __syncthreads();   // visible to all; A chunk 0 staged

    float acc[4][4][4];
    #pragma unroll
    for (int mf = 0; mf < 4; mf++)
        #pragma unroll
        for (int nf = 0; nf < 4; nf++)
            #pragma unroll
            for (int q = 0; q < 4; q++) acc[mf][nf][q] = 0.f;

    int p = 0;
    #pragma unroll
    for (int ch = 0; ch < 8; ch++) {
        const float* Ab = Abuf[p];
        const float* Wb = Wbuf[p];
        #pragma unroll
        for (int ks = 0; ks < 4; ks++) {
            uint32_t a[4][4];
            #pragma unroll
            for (int mf = 0; mf < 4; mf++) {
                int rlo = wr * 64 + mf * 16 + lq;
                int u = (ks * 2 + (lr >> 1)) ^ ((lq & 3) << 1);
                float2 lo = *(const float2*)&Ab[rlo * 32 + u * 4 + (lr & 1) * 2];
                float2 hi = *(const float2*)&Ab[(rlo + 8) * 32 + u * 4 + (lr & 1) * 2];
                a[mf][0] = __float_as_uint(lo.x);
                a[mf][1] = __float_as_uint(hi.x);
                a[mf][2] = __float_as_uint(lo.y);
                a[mf][3] = __float_as_uint(hi.y);
            }
            uint32_t b[4][2];
            #pragma unroll
            for (int nf = 0; nf < 4; nf++) {
                float2 bv = *(const float2*)&Wb[(ks * 4 + lr) * WROW
                                                + (cw * 32 + nf * 8 + lq) * 2];
                b[nf][0] = __float_as_uint(bv.x);
                b[nf][1] = __float_as_uint(bv.y);
            }
            #pragma unroll
            for (int mf = 0; mf < 4; mf++)
                #pragma unroll
                for (int nf = 0; nf < 4; nf++)
                    mma_tf32(acc[mf][nf], a[mf], b[nf]);
        }
        // stage next A (targets buffer p^1 — retired last iteration, safe)
        if (ch < 7) {
            stsA(p ^ 1);
            if (ch < 6) ldgA(ch + 2);
        }
        __syncthreads();   // ALL warps done reading Wbuf[p]/Abuf[p]; stsA visible
        if (ch + 2 < 8) { copyW(ch + 2, p); cp_commit(); }   // now safe: buf p free
        if (ch < 7) {
            if (ch + 2 < 8) cp_wait<1>(); else cp_wait<0>(); // chunk ch+1's W landed
            __syncthreads();                                 // DMA writes visible to all
        }
        p ^= 1;
    }

    // ---------------- epilogue ----------------
    #pragma unroll
    for (int mf = 0; mf < 4; mf++)
        #pragma unroll
        for (int nf = 0; nf < 4; nf++) {
            int c0 = cw * 32 + nf * 8 + 2 * lr;
            float b0v = csh[c0], b1v = csh[c0 + 1];
            acc[mf][nf][0] += b0v; acc[mf][nf][1] += b1v;
            acc[mf][nf][2] += b0v; acc[mf][nf][3] += b1v;
        }

    if (MODE == 1) {
        #pragma unroll
        for (int mf = 0; mf < 4; mf++) {
            float slo = 0.f, sslo = 0.f, shi = 0.f, sshi = 0.f;
            #pragma unroll
            for (int nf = 0; nf < 4; nf++) {
                float v0 = acc[mf][nf][0], v1 = acc[mf][nf][1];
                float v2 = acc[mf][nf][2], v3 = acc[mf][nf][3];
                slo += v0 + v1;  sslo += v0 * v0 + v1 * v1;
                shi += v2 + v3;  sshi += v2 * v2 + v3 * v3;
            }
            #pragma unroll
            for (int m = 1; m <= 2; m <<= 1) {
                slo  += __shfl_xor_sync(0xffffffffu, slo,  m);
                sslo += __shfl_xor_sync(0xffffffffu, sslo, m);
                shi  += __shfl_xor_sync(0xffffffffu, shi,  m);
                sshi += __shfl_xor_sync(0xffffffffu, sshi, m);
            }
            if (lr == 0) {
                int rlo = wr * 64 + mf * 16 + lq;
                rs [rlo * 4 + cw] = slo;       rss[rlo * 4 + cw] = sslo;
                rs [(rlo + 8) * 4 + cw] = shi; rss[(rlo + 8) * 4 + cw] = sshi;
            }
        }
        __syncthreads();
        if (tid < 128) {
            float s  = rs [tid * 4] + rs [tid * 4 + 1] + rs [tid * 4 + 2] + rs [tid * 4 + 3];
            float ss = rss[tid * 4] + rss[tid * 4 + 1] + rss[tid * 4 + 2] + rss[tid * 4 + 3];
            float mu  = s * (1.0f / H);
            float var = ss * (1.0f / H) - mu * mu;
            mus[tid] = mu;
            rstds[tid] = rsqrtf(var + 1e-5f);
        }
        __syncthreads();
        #pragma unroll
        for (int mf = 0; mf < 4; mf++) {
            int lrow = wr * 64 + mf * 16 + lq;
            float mu_lo = mus[lrow],     rd_lo = rstds[lrow];
            float mu_hi = mus[lrow + 8], rd_hi = rstds[lrow + 8];
            int glo = row0 + lrow, ghi = glo + 8;
            #pragma unroll
            for (int nf = 0; nf < 4; nf++) {
                int c0 = cw * 32 + nf * 8 + 2 * lr;
                float g0 = csh[H + c0], g1 = csh[H + c0 + 1];
                float be0 = csh[2 * H + c0], be1 = csh[2 * H + c0 + 1];
                if (glo < n) {
                    float2 o;
                    o.x = fmaxf((acc[mf][nf][0] - mu_lo) * rd_lo * g0 + be0, 0.f);
                    o.y = fmaxf((acc[mf][nf][1] - mu_lo) * rd_lo * g1 + be1, 0.f);
                    *(float2*)(g_h1 + (size_t)glo * H + c0) = o;
                }
                if (ghi < n) {
                    float2 o;
                    o.x = fmaxf((acc[mf][nf][2] - mu_hi) * rd_hi * g0 + be0, 0.f);
                    o.y = fmaxf((acc[mf][nf][3] - mu_hi) * rd_hi * g1 + be1, 0.f);
                    *(float2*)(g_h1 + (size_t)ghi * H + c0) = o;
                }
            }
        }
    } else {
        #pragma unroll
        for (int mf = 0; mf < 4; mf++) {
            int lrow = wr * 64 + mf * 16 + lq;
            int glo = row0 + lrow, ghi = glo + 8;
            int klo = 0, khi = 0;
            bool rlo = false, rhi = false;
            if (MODE == 0) {
                klo = kindsh[lrow]; khi = kindsh[lrow + 8];
                rlo = (klo != 0);   rhi = (khi != 0);
            }
            float* dst = (MODE == 0) ? g_h0 : outExt;
            #pragma unroll
            for (int nf = 0; nf < 4; nf++) {
                int c0 = cw * 32 + nf * 8 + 2 * lr;
                if (glo < n) {
                    float2 o = make_float2(acc[mf][nf][0], acc[mf][nf][1]);
                    if (MODE == 0) {
                        o.x += csh[H + klo * H + c0];
                        o.y += csh[H + klo * H + c0 + 1];
                        if (rlo) { o.x += csh[4 * H + c0]; o.y += csh[4 * H + c0 + 1]; }
                    }
                    *(float2*)(dst + (size_t)glo * H + c0) = o;
                }
                if (ghi < n) {
                    float2 o = make_float2(acc[mf][nf][2], acc[mf][nf][3]);
                    if (MODE == 0) {
                        o.x += csh[H + khi * H + c0];
                        o.y += csh[H + khi * H + c0 + 1];
                        if (rhi) { o.x += csh[4 * H + c0]; o.y += csh[4 * H + c0 + 1]; }
                    }
                    *(float2*)(dst + (size_t)ghi * H + c0) = o;
                }
            }
        }
    }
}

// ---------------------------------------------------------------------------
extern "C" void kernel_launch(void* const* d_in, const int* in_sizes, int n_in,
                              void* d_out, int out_size) {
    const float* x          = (const float*)d_in[0];
    const int*   ei         = (const int*)d_in[1];
    const int*   node_kind  = (const int*)d_in[2];
    const float* W_in       = (const float*)d_in[3];
    const float* b_in       = (const float*)d_in[4];
    const float* kind_embed = (const float*)d_in[5];
    const float* ext_seed   = (const float*)d_in[6];
    const float* Wl1        = (const float*)d_in[7];
    const float* bl1        = (const float*)d_in[8];
    const float* Wr1        = (const float*)d_in[9];
    const float* gamma      = (const float*)d_in[10];
    const float* beta       = (const float*)d_in[11];
    const float* Wl2        = (const float*)d_in[12];
    const float* bl2        = (const float*)d_in[13];
    const float* Wr2        = (const float*)d_in[14];

    int n = in_sizes[2];
    int E = in_sizes[1] / 2;

    cudaFuncSetAttribute(tc_gemm<0>, cudaFuncAttributeMaxDynamicSharedMemorySize, SM_BYTES);
    cudaFuncSetAttribute(tc_gemm<1>, cudaFuncAttributeMaxDynamicSharedMemorySize, SM_BYTES);
    cudaFuncSetAttribute(tc_gemm<2>, cudaFuncAttributeMaxDynamicSharedMemorySize, SM_BYTES);

    int ntiles = (n + 127) / 128;
    int nb256  = (n + 255) / 256;
    int eb256  = (E + 255) / 256;
    int aggblk = (n * 32 + 255) / 256;

    // ---- fork: CSR build on side stream, concurrent with prep_w + gemm0 ----
    cudaStream_t s2;
    cudaStreamCreateWithFlags(&s2, cudaStreamNonBlocking);
    cudaEvent_t e1, e2;
    cudaEventCreateWithFlags(&e1, cudaEventDisableTiming);
    cudaEventCreateWithFlags(&e2, cudaEventDisableTiming);

    cudaEventRecord(e1, 0);
    cudaStreamWaitEvent(s2, e1, 0);
    zero_cnt<<<nb256, 256, 0, s2>>>(n);
    hist_kernel<<<eb256, 256, 0, s2>>>(ei, E);
    scan1<<<nb256, 256, 0, s2>>>(n);
    scan2<<<1, 256, 0, s2>>>(nb256);
    scan3<<<nb256, 256, 0, s2>>>(n);
    fill_kernel<<<eb256, 256, 0, s2>>>(ei, E);
    cudaEventRecord(e2, s2);

    // main stream: weight prep then gemm0 (overlaps CSR)
    prep_w<<<(3 * KTOT * H + 255) / 256, 256>>>(W_in, Wl1, Wr1, Wl2, Wr2);
    tc_gemm<0><<<ntiles, TPB, SM_BYTES>>>(x, b_in, kind_embed, ext_seed,
                                          node_kind, nullptr, n);

    // ---- join: aggregate needs both h0 and CSR ----
    cudaStreamWaitEvent(0, e2, 0);
    aggregate_kernel<0><<<aggblk, 256>>>(n);
    tc_gemm<1><<<ntiles, TPB, SM_BYTES>>>(nullptr, bl1, gamma, beta,
                                          nullptr, nullptr, n);
    aggregate_kernel<1><<<aggblk, 256>>>(n);
    tc_gemm<2><<<ntiles, TPB, SM_BYTES>>>(nullptr, bl2, nullptr, nullptr,
                                          nullptr, (float*)d_out, n);
}

// round 11
// speedup vs baseline: 1.0965x; 1.0921x over previous
#include <cuda_runtime.h>
#include <cstdint>

#define NMAX 50000
#define EMAX 650000
#define H 128
#define KTOT 256
#define TPB 512
#define WROW 264   // k-pair row stride: 256 + 8 pad

// -------------------- scratch (no allocations allowed) ----------------------
__device__ float g_h0[NMAX * H];
__device__ float g_h1[NMAX * H];
__device__ float g_agg[NMAX * H];
__device__ int   g_cnt[NMAX];
__device__ int   g_off[NMAX];
__device__ int   g_cur[NMAX];
__device__ int   g_adj[EMAX];
__device__ int   g_blk[256];
__device__ __align__(16) float g_Wt[3][128 * WROW];  // tf32-rounded smem image

// -------------------- helpers ------------------------------------------------
__device__ __forceinline__ uint32_t tf32r(float x) {
    uint32_t r; asm("cvt.rna.tf32.f32 %0, %1;" : "=r"(r) : "f"(x));
    return r;
}
__device__ __forceinline__ void mma_tf32(float* d, const uint32_t* a, const uint32_t* b) {
    asm volatile("mma.sync.aligned.m16n8k8.row.col.f32.tf32.tf32.f32 "
                 "{%0,%1,%2,%3}, {%4,%5,%6,%7}, {%8,%9}, {%0,%1,%2,%3};"
                 : "+f"(d[0]), "+f"(d[1]), "+f"(d[2]), "+f"(d[3])
                 : "r"(a[0]), "r"(a[1]), "r"(a[2]), "r"(a[3]),
                   "r"(b[0]), "r"(b[1]));
}
__device__ __forceinline__ void cp16(uint32_t dst, const float* src) {
    asm volatile("cp.async.cg.shared.global [%0], [%1], 16;" :: "r"(dst), "l"(src));
}
__device__ __forceinline__ void cp_commit() {
    asm volatile("cp.async.commit_group;" ::: "memory");
}
template<int N>
__device__ __forceinline__ void cp_wait() {
    asm volatile("cp.async.wait_group %0;" :: "n"(N) : "memory");
}

// -------------------- weight prep: tf32-round into smem-image layout ---------
__global__ void prep_w(const float* __restrict__ W_in,
                       const float* __restrict__ Wl1, const float* __restrict__ Wr1,
                       const float* __restrict__ Wl2, const float* __restrict__ Wr2) {
    int i = blockIdx.x * blockDim.x + threadIdx.x;
    if (i >= 3 * KTOT * H) return;
    int col = i & 127;
    int k   = (i >> 7) & 255;
    int m   = i >> 15;
    float v;
    if (m == 0)      v = W_in[k * H + col];
    else if (m == 1) v = (k < H) ? Wl1[k * H + col] : Wr1[(k - H) * H + col];
    else             v = (k < H) ? Wl2[k * H + col] : Wr2[(k - H) * H + col];
    int c  = k >> 5, kk = k & 31;
    int pr = ((kk >> 3) << 2) | (kk & 3);
    int s  = (kk >> 2) & 1;
    g_Wt[m][(c * 16 + pr) * WROW + col * 2 + s] = __uint_as_float(tf32r(v));
}

// -------------------- CSR build ----------------------------------------------
__global__ void zero_cnt(int n) {
    int i = blockIdx.x * blockDim.x + threadIdx.x;
    if (i < n) g_cnt[i] = 0;
}
__global__ void hist_kernel(const int* __restrict__ ei, int E) {
    int e = blockIdx.x * blockDim.x + threadIdx.x;
    if (e < E) atomicAdd(&g_cnt[__ldg(ei + E + e)], 1);
}
__global__ void scan1(int n) {
    __shared__ int smv[256];
    int t = threadIdx.x;
    int i = blockIdx.x * 256 + t;
    int v = (i < n) ? g_cnt[i] : 0;
    smv[t] = v;
    __syncthreads();
    #pragma unroll
    for (int off = 1; off < 256; off <<= 1) {
        int x = (t >= off) ? smv[t - off] : 0;
        __syncthreads();
        smv[t] += x;
        __syncthreads();
    }
    if (i < n) g_off[i] = smv[t] - v;
    if (t == 255) g_blk[blockIdx.x] = smv[255];
}
__global__ void scan2(int nb) {
    __shared__ int smv[256];
    int t = threadIdx.x;
    int v = (t < nb) ? g_blk[t] : 0;
    smv[t] = v;
    __syncthreads();
    #pragma unroll
    for (int off = 1; off < 256; off <<= 1) {
        int x = (t >= off) ? smv[t - off] : 0;
        __syncthreads();
        smv[t] += x;
        __syncthreads();
    }
    if (t < nb) g_blk[t] = smv[t] - v;
}
__global__ void scan3(int n) {
    int i = blockIdx.x * blockDim.x + threadIdx.x;
    if (i < n) {
        int o = g_off[i] + g_blk[i >> 8];
        g_off[i] = o;
        g_cur[i] = o;
    }
}
__global__ void fill_kernel(const int* __restrict__ ei, int E) {
    int e = blockIdx.x * blockDim.x + threadIdx.x;
    if (e < E) {
        int s = __ldg(ei + e);
        int d = __ldg(ei + E + e);
        int p = atomicAdd(&g_cur[d], 1);
        g_adj[p] = s;
    }
}

// -------------------- CSR aggregate: mean of h[src] per dst ------------------
template<int SRC>
__global__ void aggregate_kernel(int n) {
    int gw = (blockIdx.x * blockDim.x + threadIdx.x) >> 5;
    if (gw >= n) return;
    int lane = threadIdx.x & 31;
    const float* h = (SRC == 0) ? g_h0 : g_h1;
    int start = g_off[gw];
    int c = g_cnt[gw];
    float4 acc0 = make_float4(0.f, 0.f, 0.f, 0.f);
    float4 acc1 = make_float4(0.f, 0.f, 0.f, 0.f);
    int j = 0;
    for (; j + 2 <= c; j += 2) {
        int s0 = __ldg(g_adj + start + j);
        int s1 = __ldg(g_adj + start + j + 1);
        float4 v0 = __ldg((const float4*)(h + (size_t)s0 * H) + lane);
        float4 v1 = __ldg((const float4*)(h + (size_t)s1 * H) + lane);
        acc0.x += v0.x; acc0.y += v0.y; acc0.z += v0.z; acc0.w += v0.w;
        acc1.x += v1.x; acc1.y += v1.y; acc1.z += v1.z; acc1.w += v1.w;
    }
    if (j < c) {
        int s0 = __ldg(g_adj + start + j);
        float4 v0 = __ldg((const float4*)(h + (size_t)s0 * H) + lane);
        acc0.x += v0.x; acc0.y += v0.y; acc0.z += v0.z; acc0.w += v0.w;
    }
    float sc = (c > 0) ? (1.0f / (float)c) : 0.0f;
    float4 o;
    o.x = (acc0.x + acc1.x) * sc;
    o.y = (acc0.y + acc1.y) * sc;
    o.z = (acc0.z + acc1.z) * sc;
    o.w = (acc0.w + acc1.w) * sc;
    ((float4*)(g_agg + (size_t)gw * H))[lane] = o;
}

// smem layout (floats)
#define SMF_W     0                       // 3 * 16*264 = 12672 (W ring)
#define SMF_A     12672                   // 2 * 128*32 = 8192
#define SMF_C     20864                   // 768
#define SMF_RS    21632                   // 512
#define SMF_RSS   22144                   // 512
#define SMF_MU    22656                   // 128
#define SMF_RSTD  22784                   // 128
#define SMF_KIND  22912                   // 128
#define SMF_TOTAL 23040
#define SM_BYTES  (SMF_TOTAL * 4)

// -------------- pipelined tf32 mma GEMM: R6 structure + cp.async W ring ------
// MODE 0: A=x[N,256], W=Wt0 -> h0 = ..+b_in+kind_embed[k]+relay*ext
// MODE 1: A=[agg | h0], W=Wt1 -> relu(LN(..+bl1)) -> h1
// MODE 2: A=[agg | h1], W=Wt2 -> ..+bl2 -> out
template<int MODE>
__global__ void __launch_bounds__(TPB, 1)
tc_gemm(const float* __restrict__ Aext,
        const float* __restrict__ bias,
        const float* __restrict__ aux0,   // MODE0 kind_embed / MODE1 gamma
        const float* __restrict__ aux1,   // MODE0 ext_seed   / MODE1 beta
        const int*   __restrict__ node_kind,
        float* __restrict__ outExt,
        int n)
{
    extern __shared__ float sm[];
    float* Wring[3] = { sm + SMF_W, sm + SMF_W + 16 * WROW, sm + SMF_W + 32 * WROW };
    float* Abuf[2]  = { sm + SMF_A, sm + SMF_A + 128 * 32 };
    float* csh   = sm + SMF_C;
    float* rs    = sm + SMF_RS;
    float* rss   = sm + SMF_RSS;
    float* mus   = sm + SMF_MU;
    float* rstds = sm + SMF_RSTD;
    int*   kindsh = (int*)(sm + SMF_KIND);

    const int tid = threadIdx.x;
    const int wid = tid >> 5;
    const int lid = tid & 31;
    const int lq = lid >> 2;
    const int lr = lid & 3;
    const int wr = wid & 3;        // 4 row-blocks of 32
    const int cw = wid >> 2;       // 4 col-blocks of 32
    const int row0 = blockIdx.x << 7;

    // A staging roles (R6): 4 threads per row, each 8 consecutive k floats
    const int arow = tid >> 2;     // 0..127
    const int ag   = tid & 3;      // k-group of 8
    const int agr  = row0 + arow;

    const float* Asrc = (MODE == 1) ? (const float*)g_h0 : (const float*)g_h1;
    const float* Wt = g_Wt[MODE];

    uint32_t wsh[3] = { (uint32_t)__cvta_generic_to_shared(Wring[0]),
                        (uint32_t)__cvta_generic_to_shared(Wring[1]),
                        (uint32_t)__cvta_generic_to_shared(Wring[2]) };

    float4 va, vb;

    auto ldgA = [&](int ch) {
        va = make_float4(0.f,0.f,0.f,0.f); vb = va;
        if (agr < n) {
            const float4* s;
            if (MODE == 0)   s = (const float4*)(Aext  + (size_t)agr * KTOT + ch * 32 + ag * 8);
            else if (ch < 4) s = (const float4*)(g_agg + (size_t)agr * H + ch * 32 + ag * 8);
            else             s = (const float4*)(Asrc  + (size_t)agr * H + (ch - 4) * 32 + ag * 8);
            va = __ldg(s); vb = __ldg(s + 1);
        }
    };
    auto stsA = [&](int p) {
        uint4 s0, s1;
        s0.x = tf32r(va.x); s0.y = tf32r(vb.x);
        s0.z = tf32r(va.y); s0.w = tf32r(vb.y);
        s1.x = tf32r(va.z); s1.y = tf32r(vb.z);
        s1.z = tf32r(va.w); s1.w = tf32r(vb.w);
        int u0 = (ag * 2) ^ ((arow & 3) << 1);
        uint4* d = (uint4*)&Abuf[p][arow * 32 + u0 * 4];
        d[0] = s0; d[1] = s1;
    };
    // W copy: chunk ch (16 pair-rows x 264 floats = 1056 float4) into ring slot p
    auto copyW = [&](int ch, int p) {
        const float* src = Wt + ch * 16 * WROW;
        #pragma unroll
        for (int j = 0; j < 3; j++) {
            int f4 = tid + j * TPB;
            if (f4 < 1056) {
                int off = f4 * 4;
                cp16(wsh[p] + off * 4, src + off);
            }
        }
    };

    // ---- prologue: W chunks 0,1 in flight; consts; A chunk 0 staged ----
    copyW(0, 0); cp_commit();
    copyW(1, 1); cp_commit();
    ldgA(0);
    if (tid < H) csh[tid] = __ldg(bias + tid);
    if (MODE == 0) {
        if (tid >= H && tid < H + 3 * H) csh[tid] = __ldg(aux0 + (tid - H));
        if (tid < H) csh[4 * H + tid] = __ldg(aux1 + tid);
        if (tid < 128) kindsh[tid] = (row0 + tid < n) ? __ldg(node_kind + row0 + tid) : 0;
    } else if (MODE == 1) {
        if (tid < H) { csh[H + tid] = __ldg(aux0 + tid); csh[2 * H + tid] = __ldg(aux1 + tid); }
    }
    stsA(0);
    ldgA(1);
    cp_wait<1>();      // W chunk 0 landed
    __syncthreads();

    float acc[2][4][4];
    #pragma unroll
    for (int mf = 0; mf < 2; mf++)
        #pragma unroll
        for (int nf = 0; nf < 4; nf++)
            #pragma unroll
            for (int q = 0; q < 4; q++) acc[mf][nf][q] = 0.f;

    int p = 0;
    #pragma unroll
    for (int ch = 0; ch < 8; ch++) {
        // prefetch W chunk ch+2 into ring slot (ch+2)%3 — that slot was last
        // read in chunk ch-1, retired by the barrier that ended chunk ch-1.
        if (ch + 2 < 8) { copyW(ch + 2, (ch + 2) % 3); cp_commit(); }

        const float* Ab = Abuf[p];
        const float* Wb = Wring[ch % 3];
        #pragma unroll
        for (int ks = 0; ks < 4; ks++) {
            uint32_t a[2][4];
            #pragma unroll
            for (int mf = 0; mf < 2; mf++) {
                int rlo = wr * 32 + mf * 16 + lq;
                int u = (ks * 2 + (lr >> 1)) ^ ((lq & 3) << 1);
                float2 lo = *(const float2*)&Ab[rlo * 32 + u * 4 + (lr & 1) * 2];
                float2 hi = *(const float2*)&Ab[(rlo + 8) * 32 + u * 4 + (lr & 1) * 2];
                a[mf][0] = __float_as_uint(lo.x);
                a[mf][1] = __float_as_uint(hi.x);
                a[mf][2] = __float_as_uint(lo.y);
                a[mf][3] = __float_as_uint(hi.y);
            }
            uint32_t b[4][2];
            #pragma unroll
            for (int nf = 0; nf < 4; nf++) {
                float2 bv = *(const float2*)&Wb[(ks * 4 + lr) * WROW
                                                + (cw * 32 + nf * 8 + lq) * 2];
                b[nf][0] = __float_as_uint(bv.x);
                b[nf][1] = __float_as_uint(bv.y);
            }
            #pragma unroll
            for (int mf = 0; mf < 2; mf++)
                #pragma unroll
                for (int nf = 0; nf < 4; nf++)
                    mma_tf32(acc[mf][nf], a[mf], b[nf]);
        }
        if (ch < 7) {
            stsA(p ^ 1);                 // buffer p^1 retired at end of ch-1
            if (ch < 6) ldgA(ch + 2);
            if (ch + 2 < 8) cp_wait<1>(); else cp_wait<0>();  // chunk ch+1 landed
        }
        __syncthreads();
        p ^= 1;
    }

    // ---------------- epilogue (identical to R6) ----------------
    #pragma unroll
    for (int mf = 0; mf < 2; mf++)
        #pragma unroll
        for (int nf = 0; nf < 4; nf++) {
            int c0 = cw * 32 + nf * 8 + 2 * lr;
            float b0v = csh[c0], b1v = csh[c0 + 1];
            acc[mf][nf][0] += b0v; acc[mf][nf][1] += b1v;
            acc[mf][nf][2] += b0v; acc[mf][nf][3] += b1v;
        }

    if (MODE == 1) {
        #pragma unroll
        for (int mf = 0; mf < 2; mf++) {
            float slo = 0.f, sslo = 0.f, shi = 0.f, sshi = 0.f;
            #pragma unroll
            for (int nf = 0; nf < 4; nf++) {
                float v0 = acc[mf][nf][0], v1 = acc[mf][nf][1];
                float v2 = acc[mf][nf][2], v3 = acc[mf][nf][3];
                slo += v0 + v1;  sslo += v0 * v0 + v1 * v1;
                shi += v2 + v3;  sshi += v2 * v2 + v3 * v3;
            }
            #pragma unroll
            for (int m = 1; m <= 2; m <<= 1) {
                slo  += __shfl_xor_sync(0xffffffffu, slo,  m);
                sslo += __shfl_xor_sync(0xffffffffu, sslo, m);
                shi  += __shfl_xor_sync(0xffffffffu, shi,  m);
                sshi += __shfl_xor_sync(0xffffffffu, sshi, m);
            }
            if (lr == 0) {
                int rlo = wr * 32 + mf * 16 + lq;
                rs [rlo * 4 + cw] = slo;       rss[rlo * 4 + cw] = sslo;
                rs [(rlo + 8) * 4 + cw] = shi; rss[(rlo + 8) * 4 + cw] = sshi;
            }
        }
        __syncthreads();
        if (tid < 128) {
            float s  = rs [tid * 4] + rs [tid * 4 + 1] + rs [tid * 4 + 2] + rs [tid * 4 + 3];
            float ss = rss[tid * 4] + rss[tid * 4 + 1] + rss[tid * 4 + 2] + rss[tid * 4 + 3];
            float mu  = s * (1.0f / H);
            float var = ss * (1.0f / H) - mu * mu;
            mus[tid] = mu;
            rstds[tid] = rsqrtf(var + 1e-5f);
        }
        __syncthreads();
        #pragma unroll
        for (int mf = 0; mf < 2; mf++) {
            int lrow = wr * 32 + mf * 16 + lq;
            float mu_lo = mus[lrow],     rd_lo = rstds[lrow];
            float mu_hi = mus[lrow + 8], rd_hi = rstds[lrow + 8];
            int glo = row0 + lrow, ghi = glo + 8;
            #pragma unroll
            for (int nf = 0; nf < 4; nf++) {
                int c0 = cw * 32 + nf * 8 + 2 * lr;
                float g0 = csh[H + c0], g1 = csh[H + c0 + 1];
                float be0 = csh[2 * H + c0], be1 = csh[2 * H + c0 + 1];
                if (glo < n) {
                    float2 o;
                    o.x = fmaxf((acc[mf][nf][0] - mu_lo) * rd_lo * g0 + be0, 0.f);
                    o.y = fmaxf((acc[mf][nf][1] - mu_lo) * rd_lo * g1 + be1, 0.f);
                    *(float2*)(g_h1 + (size_t)glo * H + c0) = o;
                }
                if (ghi < n) {
                    float2 o;
                    o.x = fmaxf((acc[mf][nf][2] - mu_hi) * rd_hi * g0 + be0, 0.f);
                    o.y = fmaxf((acc[mf][nf][3] - mu_hi) * rd_hi * g1 + be1, 0.f);
                    *(float2*)(g_h1 + (size_t)ghi * H + c0) = o;
                }
            }
        }
    } else {
        #pragma unroll
        for (int mf = 0; mf < 2; mf++) {
            int lrow = wr * 32 + mf * 16 + lq;
            int glo = row0 + lrow, ghi = glo + 8;
            int klo = 0, khi = 0;
            bool rlo = false, rhi = false;
            if (MODE == 0) {
                klo = kindsh[lrow]; khi = kindsh[lrow + 8];
                rlo = (klo != 0);   rhi = (khi != 0);
            }
            float* dst = (MODE == 0) ? g_h0 : outExt;
            #pragma unroll
            for (int nf = 0; nf < 4; nf++) {
                int c0 = cw * 32 + nf * 8 + 2 * lr;
                if (glo < n) {
                    float2 o = make_float2(acc[mf][nf][0], acc[mf][nf][1]);
                    if (MODE == 0) {
                        o.x += csh[H + klo * H + c0];
                        o.y += csh[H + klo * H + c0 + 1];
                        if (rlo) { o.x += csh[4 * H + c0]; o.y += csh[4 * H + c0 + 1]; }
                    }
                    *(float2*)(dst + (size_t)glo * H + c0) = o;
                }
                if (ghi < n) {
                    float2 o = make_float2(acc[mf][nf][2], acc[mf][nf][3]);
                    if (MODE == 0) {
                        o.x += csh[H + khi * H + c0];
                        o.y += csh[H + khi * H + c0 + 1];
                        if (rhi) { o.x += csh[4 * H + c0]; o.y += csh[4 * H + c0 + 1]; }
                    }
                    *(float2*)(dst + (size_t)ghi * H + c0) = o;
                }
            }
        }
    }
}

// ---------------------------------------------------------------------------
extern "C" void kernel_launch(void* const* d_in, const int* in_sizes, int n_in,
                              void* d_out, int out_size) {
    const float* x          = (const float*)d_in[0];
    const int*   ei         = (const int*)d_in[1];
    const int*   node_kind  = (const int*)d_in[2];
    const float* W_in       = (const float*)d_in[3];
    const float* b_in       = (const float*)d_in[4];
    const float* kind_embed = (const float*)d_in[5];
    const float* ext_seed   = (const float*)d_in[6];
    const float* Wl1        = (const float*)d_in[7];
    const float* bl1        = (const float*)d_in[8];
    const float* Wr1        = (const float*)d_in[9];
    const float* gamma      = (const float*)d_in[10];
    const float* beta       = (const float*)d_in[11];
    const float* Wl2        = (const float*)d_in[12];
    const float* bl2        = (const float*)d_in[13];
    const float* Wr2        = (const float*)d_in[14];

    int n = in_sizes[2];
    int E = in_sizes[1] / 2;

    cudaFuncSetAttribute(tc_gemm<0>, cudaFuncAttributeMaxDynamicSharedMemorySize, SM_BYTES);
    cudaFuncSetAttribute(tc_gemm<1>, cudaFuncAttributeMaxDynamicSharedMemorySize, SM_BYTES);
    cudaFuncSetAttribute(tc_gemm<2>, cudaFuncAttributeMaxDynamicSharedMemorySize, SM_BYTES);

    int ntiles = (n + 127) / 128;
    int nb256  = (n + 255) / 256;
    int eb256  = (E + 255) / 256;
    int aggblk = (n * 32 + 255) / 256;

    // ---- fork: CSR build on side stream, concurrent with prep_w + gemm0 ----
    cudaStream_t s2;
    cudaStreamCreateWithFlags(&s2, cudaStreamNonBlocking);
    cudaEvent_t e1, e2;
    cudaEventCreateWithFlags(&e1, cudaEventDisableTiming);
    cudaEventCreateWithFlags(&e2, cudaEventDisableTiming);

    cudaEventRecord(e1, 0);
    cudaStreamWaitEvent(s2, e1, 0);
    zero_cnt<<<nb256, 256, 0, s2>>>(n);
    hist_kernel<<<eb256, 256, 0, s2>>>(ei, E);
    scan1<<<nb256, 256, 0, s2>>>(n);
    scan2<<<1, 256, 0, s2>>>(nb256);
    scan3<<<nb256, 256, 0, s2>>>(n);
    fill_kernel<<<eb256, 256, 0, s2>>>(ei, E);
    cudaEventRecord(e2, s2);

    // main stream: weight prep then gemm0 (overlaps CSR)
    prep_w<<<(3 * KTOT * H + 255) / 256, 256>>>(W_in, Wl1, Wr1, Wl2, Wr2);
    tc_gemm<0><<<ntiles, TPB, SM_BYTES>>>(x, b_in, kind_embed, ext_seed,
                                          node_kind, nullptr, n);

    // ---- join: aggregate needs both h0 and CSR ----
    cudaStreamWaitEvent(0, e2, 0);
    aggregate_kernel<0><<<aggblk, 256>>>(n);
    tc_gemm<1><<<ntiles, TPB, SM_BYTES>>>(nullptr, bl1, gamma, beta,
                                          nullptr, nullptr, n);
    aggregate_kernel<1><<<aggblk, 256>>>(n);
    tc_gemm<2><<<ntiles, TPB, SM_BYTES>>>(nullptr, bl2, nullptr, nullptr,
                                          nullptr, (float*)d_out, n);
}